// round 1
// baseline (speedup 1.0000x reference)
#include <cuda_runtime.h>
#include <cuda_bf16.h>
#include <math.h>

#define NL 6
#define B  8
#define T  4
#define L  2048
#define H  16
#define D  64
#define E  1024       // H*D
#define FF 4096
#define INDIM 32
#define NTOK 32       // B*T

// -------- scratch (device globals; no allocation allowed) --------
__device__ float g_x   [NTOK * E];
__device__ float g_xn  [NTOK * E];
__device__ float g_qkv [NTOK * 3 * E];
__device__ float g_attn[NTOK * E];
__device__ float g_h   [NTOK * FF];
__device__ float g_seq [NTOK * INDIM];

// -------- bulk cache copy with NaN cleaning (float4) --------
__global__ void cache_copy_kernel(const float4* __restrict__ in,
                                  float4* __restrict__ out, long n)
{
    long i = (long)blockIdx.x * blockDim.x + threadIdx.x;
    if (i < n) {
        float4 v = in[i];
        v.x = isnan(v.x) ? 0.0f : v.x;
        v.y = isnan(v.y) ? 0.0f : v.y;
        v.z = isnan(v.z) ? 0.0f : v.z;
        v.w = isnan(v.w) ? 0.0f : v.w;
        out[i] = v;
    }
}

// -------- sequence prep: NaN -> bos embedding --------
__global__ void prep_seq_kernel(const float* __restrict__ seq,
                                const float* __restrict__ bos,
                                float* __restrict__ out)
{
    int i = blockIdx.x * 256 + threadIdx.x; // 1024 total
    float v = seq[i];
    out[i] = isnan(v) ? bos[i & (INDIM - 1)] : v;
}

// -------- skinny GEMM: Y[32,N] = X[32,K] @ W[N,K]^T --------
// ACT: 0 none, 1 exact gelu.  ACC: 0 store, 1 accumulate into Y.
template<int ACT, int ACC>
__global__ void gemm32_kernel(const float* __restrict__ X,
                              const float* __restrict__ W,
                              float* __restrict__ Y, int K, int N)
{
    __shared__ float Xs[32][33];
    __shared__ float Ws[32][33];
    int tid  = threadIdx.x;          // 256 threads
    int col0 = blockIdx.x * 32;
    int col  = tid & 31;
    int rg   = tid >> 5;             // 0..7
    float a0 = 0.f, a1 = 0.f, a2 = 0.f, a3 = 0.f;

    for (int k0 = 0; k0 < K; k0 += 32) {
        #pragma unroll
        for (int e = tid; e < 1024; e += 256) {
            int r = e >> 5, kk = e & 31;
            Xs[r][kk] = X[(size_t)r * K + k0 + kk];
            Ws[r][kk] = W[(size_t)(col0 + r) * K + k0 + kk];
        }
        __syncthreads();
        #pragma unroll
        for (int kk = 0; kk < 32; kk++) {
            float wv = Ws[col][kk];
            a0 += Xs[rg      ][kk] * wv;
            a1 += Xs[rg +  8 ][kk] * wv;
            a2 += Xs[rg + 16 ][kk] * wv;
            a3 += Xs[rg + 24 ][kk] * wv;
        }
        __syncthreads();
    }
    float acc[4] = {a0, a1, a2, a3};
    #pragma unroll
    for (int j = 0; j < 4; j++) {
        int r = rg + 8 * j;
        float v = acc[j];
        if (ACT == 1) v = 0.5f * v * (1.0f + erff(v * 0.70710678118654752f));
        float* p = Y + (size_t)r * N + col0 + col;
        if (ACC) *p += v; else *p = v;
    }
}

// -------- LayerNorm over E=1024, one block per token --------
__global__ void ln_kernel(const float* __restrict__ X,
                          const float* __restrict__ w,
                          const float* __restrict__ b,
                          float* __restrict__ Y)
{
    int tok = blockIdx.x;
    int tid = threadIdx.x; // 256
    const float* x = X + (size_t)tok * E;
    float v[4];
    float s = 0.f;
    #pragma unroll
    for (int j = 0; j < 4; j++) { v[j] = x[tid + 256 * j]; s += v[j]; }
    __shared__ float red[256];
    red[tid] = s; __syncthreads();
    for (int o = 128; o > 0; o >>= 1) { if (tid < o) red[tid] += red[tid + o]; __syncthreads(); }
    float mean = red[0] * (1.0f / E);
    __syncthreads();
    float s2 = 0.f;
    #pragma unroll
    for (int j = 0; j < 4; j++) { float d = v[j] - mean; s2 += d * d; }
    red[tid] = s2; __syncthreads();
    for (int o = 128; o > 0; o >>= 1) { if (tid < o) red[tid] += red[tid + o]; __syncthreads(); }
    float r = rsqrtf(red[0] * (1.0f / E) + 1e-5f);
    #pragma unroll
    for (int j = 0; j < 4; j++) {
        int idx = tid + 256 * j;
        Y[(size_t)tok * E + idx] = (v[j] - mean) * r * w[idx] + b[idx];
    }
}

// -------- RoPE (q in-place) + scatter rotated k and v into output cache --------
__global__ void rope_scatter_kernel(float* __restrict__ qkv,
                                    const int* __restrict__ pos_l,
                                    float* __restrict__ kcache,
                                    float* __restrict__ vcache)
{
    int id = blockIdx.x * 256 + threadIdx.x;  // B*T*H*32 = 16384
    int j = id & 31;
    int h = (id >> 5) & 15;
    int t = (id >> 9) & 3;
    int b = id >> 11;
    int pos = pos_l[b];
    float freq = expf(-(float)j * (logf(10000.0f) / 32.0f));
    float ang = (float)(pos + t) * freq;
    float sn, cs;
    sincosf(ang, &sn, &cs);
    float* qp = qkv + ((size_t)(b * T + t) * 3 * E) + h * D + 2 * j;
    float* kp = qp + E;
    float* vp = qp + 2 * E;
    float qr = qp[0], qi = qp[1];
    qp[0] = qr * cs - qi * sn;
    qp[1] = qr * sn + qi * cs;
    float kr = kp[0], ki = kp[1];
    float kor = kr * cs - ki * sn;
    float koi = kr * sn + ki * cs;
    int slot = (pos + t) % L;
    size_t coff = ((size_t)b * L + slot) * E + h * D + 2 * j;
    kcache[coff]     = kor;
    kcache[coff + 1] = koi;
    vcache[coff]     = vp[0];
    vcache[coff + 1] = vp[1];
}

// -------- Attention: one block per (b,h), 256 threads --------
#define SMAX 1056
__global__ void attn_kernel(const float* __restrict__ qkv,
                            const float* __restrict__ kc,
                            const float* __restrict__ vc,
                            const int* __restrict__ pos_l,
                            float* __restrict__ out)
{
    __shared__ float qs[4][64];
    __shared__ float sc[4][SMAX];
    __shared__ float red[256];
    __shared__ float inv[4];
    int bh = blockIdx.x;
    int b = bh >> 4, h = bh & 15;
    int tid = threadIdx.x;
    int pos = pos_l[b];
    int slen = pos + T;

    {
        int t = tid >> 6, d = tid & 63;
        qs[t][d] = qkv[((size_t)(b * T + t) * 3 * E) + h * D + d];
    }
    __syncthreads();

    const float scale = 0.125f; // 1/sqrt(64)
    for (int s = tid; s < slen; s += 256) {
        const float4* kr = (const float4*)(kc + ((size_t)b * L + s) * E + h * D);
        float d0 = 0.f, d1 = 0.f, d2 = 0.f, d3 = 0.f;
        #pragma unroll
        for (int i4 = 0; i4 < 16; i4++) {
            float4 kv = kr[i4];
            int d = i4 * 4;
            d0 += qs[0][d] * kv.x + qs[0][d+1] * kv.y + qs[0][d+2] * kv.z + qs[0][d+3] * kv.w;
            d1 += qs[1][d] * kv.x + qs[1][d+1] * kv.y + qs[1][d+2] * kv.z + qs[1][d+3] * kv.w;
            d2 += qs[2][d] * kv.x + qs[2][d+1] * kv.y + qs[2][d+2] * kv.z + qs[2][d+3] * kv.w;
            d3 += qs[3][d] * kv.x + qs[3][d+1] * kv.y + qs[3][d+2] * kv.z + qs[3][d+3] * kv.w;
        }
        sc[0][s] = (s <= pos + 0) ? d0 * scale : -1e30f;
        sc[1][s] = (s <= pos + 1) ? d1 * scale : -1e30f;
        sc[2][s] = (s <= pos + 2) ? d2 * scale : -1e30f;
        sc[3][s] = (s <= pos + 3) ? d3 * scale : -1e30f;
    }
    __syncthreads();

    for (int t = 0; t < 4; t++) {
        float m = -1e30f;
        for (int s = tid; s < slen; s += 256) m = fmaxf(m, sc[t][s]);
        red[tid] = m; __syncthreads();
        for (int o = 128; o > 0; o >>= 1) { if (tid < o) red[tid] = fmaxf(red[tid], red[tid + o]); __syncthreads(); }
        m = red[0];
        __syncthreads();
        float ssum = 0.f;
        for (int s = tid; s < slen; s += 256) {
            float e = expf(sc[t][s] - m);
            sc[t][s] = e;
            ssum += e;
        }
        red[tid] = ssum; __syncthreads();
        for (int o = 128; o > 0; o >>= 1) { if (tid < o) red[tid] += red[tid + o]; __syncthreads(); }
        if (tid == 0) inv[t] = 1.0f / red[0];
        __syncthreads();
    }

    int t = tid >> 6, d = tid & 63;
    const float* vp = vc + (size_t)b * L * E + h * D + d;
    float acc = 0.f;
    int s = 0;
    for (; s + 4 <= slen; s += 4) {
        float v0 = vp[(size_t)(s    ) * E];
        float v1 = vp[(size_t)(s + 1) * E];
        float v2 = vp[(size_t)(s + 2) * E];
        float v3 = vp[(size_t)(s + 3) * E];
        acc += sc[t][s] * v0 + sc[t][s+1] * v1 + sc[t][s+2] * v2 + sc[t][s+3] * v3;
    }
    for (; s < slen; s++) acc += sc[t][s] * vp[(size_t)s * E];
    out[((size_t)(b * T + t) * E) + h * D + d] = acc * inv[t];
}

// -------- eos: dot(x_ln, eos_w) + eos_b, one block per token --------
__global__ void eos_kernel(const float* __restrict__ x,
                           const float* __restrict__ ew,
                           const float* __restrict__ eb,
                           float* __restrict__ out_eos)
{
    int tok = blockIdx.x;
    int tid = threadIdx.x; // 256
    float s = 0.f;
    #pragma unroll
    for (int j = 0; j < 4; j++) {
        int idx = tid + 256 * j;
        s += x[(size_t)tok * E + idx] * ew[idx];
    }
    __shared__ float red[256];
    red[tid] = s; __syncthreads();
    for (int o = 128; o > 0; o >>= 1) { if (tid < o) red[tid] += red[tid + o]; __syncthreads(); }
    if (tid == 0) out_eos[tok] = red[0] + eb[0];
}

// -------- new positions = positions + T, as float --------
__global__ void pos_kernel(const int* __restrict__ positions, float* __restrict__ out)
{
    int i = threadIdx.x;
    if (i < NL * B) out[i] = (float)(positions[i] + T);
}

extern "C" void kernel_launch(void* const* d_in, const int* in_sizes, int n_in,
                              void* d_out, int out_size)
{
    const float* seq       = (const float*)d_in[0];
    const float* bos       = (const float*)d_in[1];
    const float* caches    = (const float*)d_in[2];
    const int*   positions = (const int*)  d_in[3];
    const float* in_w      = (const float*)d_in[4];
    const float* ip_w      = (const float*)d_in[5];
    const float* op_w      = (const float*)d_in[6];
    const float* n1w       = (const float*)d_in[7];
    const float* n1b       = (const float*)d_in[8];
    const float* n2w       = (const float*)d_in[9];
    const float* n2b       = (const float*)d_in[10];
    const float* l1_w      = (const float*)d_in[11];
    const float* l2_w      = (const float*)d_in[12];
    const float* on_w      = (const float*)d_in[13];
    const float* on_b      = (const float*)d_in[14];
    const float* eos_w     = (const float*)d_in[15];
    const float* eos_b     = (const float*)d_in[16];

    float* out = (float*)d_out;
    const size_t cache_elems = (size_t)NL * 2 * B * L * E;
    float* out_x     = out;
    float* out_eos   = out + (size_t)NTOK * E;
    float* out_cache = out_eos + NTOK;
    float* out_pos   = out_cache + cache_elems;

    float *px, *pxn, *pqkv, *pattn, *ph, *pseq;
    cudaGetSymbolAddress((void**)&px,    g_x);
    cudaGetSymbolAddress((void**)&pxn,   g_xn);
    cudaGetSymbolAddress((void**)&pqkv,  g_qkv);
    cudaGetSymbolAddress((void**)&pattn, g_attn);
    cudaGetSymbolAddress((void**)&ph,    g_h);
    cudaGetSymbolAddress((void**)&pseq,  g_seq);

    // bulk cache copy (input caches -> output new_caches) with NaN cleaning
    long nf4 = (long)(cache_elems / 4);
    cache_copy_kernel<<<(unsigned)((nf4 + 255) / 256), 256>>>((const float4*)caches,
                                                              (float4*)out_cache, nf4);

    prep_seq_kernel<<<4, 256>>>(seq, bos, pseq);
    // embed: x = seq' @ in_w^T   (K=32, N=1024)
    gemm32_kernel<0,0><<<E / 32, 256>>>(pseq, in_w, px, INDIM, E);

    for (int i = 0; i < NL; i++) {
        const float* ipw = ip_w + (size_t)i * 3 * E * E;
        const float* opw = op_w + (size_t)i * E * E;
        const float* l1  = l1_w + (size_t)i * FF * E;
        const float* l2  = l2_w + (size_t)i * E * FF;
        float* kcache = out_cache + ((size_t)i * 2 + 0) * B * L * E;
        float* vcache = out_cache + ((size_t)i * 2 + 1) * B * L * E;
        const int* posl = positions + i * B;

        ln_kernel<<<NTOK, 256>>>(px, n1w + (size_t)i * E, n1b + (size_t)i * E, pxn);
        gemm32_kernel<0,0><<<3 * E / 32, 256>>>(pxn, ipw, pqkv, E, 3 * E);
        rope_scatter_kernel<<<64, 256>>>(pqkv, posl, kcache, vcache);
        attn_kernel<<<B * H, 256>>>(pqkv, kcache, vcache, posl, pattn);
        gemm32_kernel<0,1><<<E / 32, 256>>>(pattn, opw, px, E, E);
        ln_kernel<<<NTOK, 256>>>(px, n2w + (size_t)i * E, n2b + (size_t)i * E, pxn);
        gemm32_kernel<1,0><<<FF / 32, 256>>>(pxn, l1, ph, E, FF);
        gemm32_kernel<0,1><<<E / 32, 256>>>(ph, l2, px, FF, E);
    }

    // final layernorm directly into output x region
    ln_kernel<<<NTOK, 256>>>(px, on_w, on_b, out_x);
    eos_kernel<<<NTOK, 256>>>(out_x, eos_w, eos_b, out_eos);
    pos_kernel<<<1, 64>>>(positions, out_pos);
}

// round 2
// speedup vs baseline: 3.9642x; 3.9642x over previous
#include <cuda_runtime.h>
#include <cuda_bf16.h>
#include <math.h>

#define NL 6
#define B  8
#define T  4
#define L  2048
#define H  16
#define D  64
#define E  1024
#define FF 4096
#define INDIM 32
#define NTOK 32

// -------- scratch (device globals) --------
__device__ float g_x   [NTOK * E];
__device__ float g_xn  [NTOK * E];
__device__ float g_qkv [NTOK * 3 * E];
__device__ float g_attn[NTOK * E];
__device__ float g_h   [NTOK * FF];
__device__ float g_seq [NTOK * INDIM];
__device__ float g_part[4 * NTOK * FF];   // split-K partials (max 4*32*4096)

// -------- bulk cache copy with NaN cleaning (float4) --------
__global__ void cache_copy_kernel(const float4* __restrict__ in,
                                  float4* __restrict__ out, long n)
{
    long i = (long)blockIdx.x * blockDim.x + threadIdx.x;
    if (i < n) {
        float4 v = in[i];
        v.x = isnan(v.x) ? 0.0f : v.x;
        v.y = isnan(v.y) ? 0.0f : v.y;
        v.z = isnan(v.z) ? 0.0f : v.z;
        v.w = isnan(v.w) ? 0.0f : v.w;
        out[i] = v;
    }
}

__global__ void prep_seq_kernel(const float* __restrict__ seq,
                                const float* __restrict__ bos,
                                float* __restrict__ out)
{
    int i = blockIdx.x * 256 + threadIdx.x;
    float v = seq[i];
    out[i] = isnan(v) ? bos[i & (INDIM - 1)] : v;
}

// ======== GEMM: Y[32,N] = X[32,K] @ W[N,K]^T ========
// block = 256 thr (8 warps), 32 cols/block, lane = row.
// Grid: (N/32, KSPLIT). Register double-buffered k-chunks of 32.
// KSPLIT==1: epilogue (ACT/ACC) applied directly. Else write partials.
template<int ACT, int ACC, int KSPLIT>
__global__ void gemv_kernel(const float* __restrict__ X,
                            const float* __restrict__ W,
                            float* __restrict__ Y,
                            float* __restrict__ part,
                            int K, int N)
{
    __shared__ float Xs[32][33];   // scalar access, conflict-free
    __shared__ float Ws[32][36];   // float4-aligned rows (144B)

    const int t    = threadIdx.x;
    const int lane = t & 31;              // = output row
    const int c0   = (t >> 5) * 4;        // this warp's 4 columns (0..28)
    const int n0   = blockIdx.x * 32;
    const int Kc   = K / KSPLIT;
    const int kbase = blockIdx.y * Kc;
    const int nch  = Kc >> 5;

    const int lrow = t >> 3;              // load row (X) / load col (W)
    const int k4   = (t & 7) * 4;

    const float4* xg = (const float4*)(X + (size_t)lrow * K + kbase + k4);
    const float4* wg = (const float4*)(W + (size_t)(n0 + lrow) * K + kbase + k4);
    float4 xr = *xg;
    float4 wr = *wg;

    float a0 = 0.f, a1 = 0.f, a2 = 0.f, a3 = 0.f;

    for (int ch = 0; ch < nch; ch++) {
        Xs[lrow][k4]     = xr.x;
        Xs[lrow][k4 + 1] = xr.y;
        Xs[lrow][k4 + 2] = xr.z;
        Xs[lrow][k4 + 3] = xr.w;
        *(float4*)&Ws[lrow][k4] = wr;
        __syncthreads();
        if (ch + 1 < nch) { xg += 8; wg += 8; xr = *xg; wr = *wg; }

        float xv[32];
        #pragma unroll
        for (int j = 0; j < 32; j++) xv[j] = Xs[lane][j];

        #pragma unroll
        for (int j4 = 0; j4 < 8; j4++) {
            float4 w0 = *(const float4*)&Ws[c0    ][j4 * 4];
            float4 w1 = *(const float4*)&Ws[c0 + 1][j4 * 4];
            float4 w2 = *(const float4*)&Ws[c0 + 2][j4 * 4];
            float4 w3 = *(const float4*)&Ws[c0 + 3][j4 * 4];
            float x0 = xv[j4 * 4], x1 = xv[j4 * 4 + 1], x2 = xv[j4 * 4 + 2], x3 = xv[j4 * 4 + 3];
            a0 += x0 * w0.x + x1 * w0.y + x2 * w0.z + x3 * w0.w;
            a1 += x0 * w1.x + x1 * w1.y + x2 * w1.z + x3 * w1.w;
            a2 += x0 * w2.x + x1 * w2.y + x2 * w2.z + x3 * w2.w;
            a3 += x0 * w3.x + x1 * w3.y + x2 * w3.z + x3 * w3.w;
        }
        __syncthreads();
    }

    float acc[4] = {a0, a1, a2, a3};
    if (KSPLIT == 1) {
        #pragma unroll
        for (int c = 0; c < 4; c++) {
            float v = acc[c];
            if (ACT == 1) v = 0.5f * v * (1.0f + erff(v * 0.70710678118654752f));
            float* p = Y + (size_t)lane * N + n0 + c0 + c;
            if (ACC) *p += v; else *p = v;
        }
    } else {
        #pragma unroll
        for (int c = 0; c < 4; c++)
            part[((size_t)blockIdx.y * 32 + lane) * N + n0 + c0 + c] = acc[c];
    }
}

// sum split-K partials, optional act / accumulate
template<int ACT, int ACC, int KS>
__global__ void reduce_kernel(const float* __restrict__ part,
                              float* __restrict__ Y, int N)
{
    int i = blockIdx.x * 256 + threadIdx.x;   // over 32*N
    if (i >= 32 * N) return;
    int r = i / N, n = i - r * N;
    float s = 0.f;
    #pragma unroll
    for (int k = 0; k < KS; k++) s += part[((size_t)k * 32 + r) * N + n];
    if (ACT == 1) s = 0.5f * s * (1.0f + erff(s * 0.70710678118654752f));
    if (ACC) Y[i] += s; else Y[i] = s;
}

// -------- LayerNorm, one block(256) per token --------
__global__ void ln_kernel(const float* __restrict__ X,
                          const float* __restrict__ w,
                          const float* __restrict__ b,
                          float* __restrict__ Y)
{
    int tok = blockIdx.x;
    int tid = threadIdx.x;
    const float* x = X + (size_t)tok * E;
    float v[4];
    float s = 0.f;
    #pragma unroll
    for (int j = 0; j < 4; j++) { v[j] = x[tid + 256 * j]; s += v[j]; }
    #pragma unroll
    for (int o = 16; o > 0; o >>= 1) s += __shfl_xor_sync(0xffffffffu, s, o);
    __shared__ float ws[8];
    if ((tid & 31) == 0) ws[tid >> 5] = s;
    __syncthreads();
    float tot = ws[0] + ws[1] + ws[2] + ws[3] + ws[4] + ws[5] + ws[6] + ws[7];
    float mean = tot * (1.0f / E);
    float s2 = 0.f;
    #pragma unroll
    for (int j = 0; j < 4; j++) { float d = v[j] - mean; s2 += d * d; }
    #pragma unroll
    for (int o = 16; o > 0; o >>= 1) s2 += __shfl_xor_sync(0xffffffffu, s2, o);
    __syncthreads();
    if ((tid & 31) == 0) ws[tid >> 5] = s2;
    __syncthreads();
    float var = (ws[0] + ws[1] + ws[2] + ws[3] + ws[4] + ws[5] + ws[6] + ws[7]) * (1.0f / E);
    float r = rsqrtf(var + 1e-5f);
    #pragma unroll
    for (int j = 0; j < 4; j++) {
        int idx = tid + 256 * j;
        Y[(size_t)tok * E + idx] = (v[j] - mean) * r * w[idx] + b[idx];
    }
}

// -------- RoPE + scatter into output cache --------
__global__ void rope_scatter_kernel(float* __restrict__ qkv,
                                    const int* __restrict__ pos_l,
                                    float* __restrict__ kcache,
                                    float* __restrict__ vcache)
{
    int id = blockIdx.x * 256 + threadIdx.x;  // 16384
    int j = id & 31;
    int h = (id >> 5) & 15;
    int t = (id >> 9) & 3;
    int b = id >> 11;
    int pos = pos_l[b];
    float freq = __expf(-(float)j * (logf(10000.0f) / 32.0f));
    float ang = (float)(pos + t) * freq;
    float sn, cs;
    sincosf(ang, &sn, &cs);
    float* qp = qkv + ((size_t)(b * T + t) * 3 * E) + h * D + 2 * j;
    float* kp = qp + E;
    float* vp = qp + 2 * E;
    float qr = qp[0], qi = qp[1];
    qp[0] = qr * cs - qi * sn;
    qp[1] = qr * sn + qi * cs;
    float kr = kp[0], ki = kp[1];
    int slot = (pos + t) % L;
    size_t coff = ((size_t)b * L + slot) * E + h * D + 2 * j;
    kcache[coff]     = kr * cs - ki * sn;
    kcache[coff + 1] = kr * sn + ki * cs;
    vcache[coff]     = vp[0];
    vcache[coff + 1] = vp[1];
}

// -------- Attention: one block per (b,h), 256 threads --------
#define SMAX 1056
__global__ void attn_kernel(const float* __restrict__ qkv,
                            const float* __restrict__ kc,
                            const float* __restrict__ vc,
                            const int* __restrict__ pos_l,
                            float* __restrict__ out)
{
    __shared__ float qs[4][64];
    __shared__ float sc[4][SMAX];
    __shared__ float red[256];
    __shared__ float inv[4];
    __shared__ float vpart[4][4][64];
    int bh = blockIdx.x;
    int b = bh >> 4, h = bh & 15;
    int tid = threadIdx.x;
    int pos = pos_l[b];
    int slen = pos + T;

    {
        int t = tid >> 6, d = tid & 63;
        qs[t][d] = qkv[((size_t)(b * T + t) * 3 * E) + h * D + d];
    }
    __syncthreads();

    const float scale = 0.125f;
    for (int s = tid; s < slen; s += 256) {
        const float4* kr = (const float4*)(kc + ((size_t)b * L + s) * E + h * D);
        float d0 = 0.f, d1 = 0.f, d2 = 0.f, d3 = 0.f;
        #pragma unroll
        for (int i4 = 0; i4 < 16; i4++) {
            float4 kv = kr[i4];
            int d = i4 * 4;
            d0 += qs[0][d] * kv.x + qs[0][d+1] * kv.y + qs[0][d+2] * kv.z + qs[0][d+3] * kv.w;
            d1 += qs[1][d] * kv.x + qs[1][d+1] * kv.y + qs[1][d+2] * kv.z + qs[1][d+3] * kv.w;
            d2 += qs[2][d] * kv.x + qs[2][d+1] * kv.y + qs[2][d+2] * kv.z + qs[2][d+3] * kv.w;
            d3 += qs[3][d] * kv.x + qs[3][d+1] * kv.y + qs[3][d+2] * kv.z + qs[3][d+3] * kv.w;
        }
        sc[0][s] = (s <= pos + 0) ? d0 * scale : -1e30f;
        sc[1][s] = (s <= pos + 1) ? d1 * scale : -1e30f;
        sc[2][s] = (s <= pos + 2) ? d2 * scale : -1e30f;
        sc[3][s] = (s <= pos + 3) ? d3 * scale : -1e30f;
    }
    __syncthreads();

    #pragma unroll
    for (int t = 0; t < 4; t++) {
        float m = -1e30f;
        for (int s = tid; s < slen; s += 256) m = fmaxf(m, sc[t][s]);
        #pragma unroll
        for (int o = 16; o > 0; o >>= 1) m = fmaxf(m, __shfl_xor_sync(0xffffffffu, m, o));
        if ((tid & 31) == 0) red[tid >> 5] = m;
        __syncthreads();
        m = fmaxf(fmaxf(fmaxf(red[0], red[1]), fmaxf(red[2], red[3])),
                  fmaxf(fmaxf(red[4], red[5]), fmaxf(red[6], red[7])));
        float ssum = 0.f;
        for (int s = tid; s < slen; s += 256) {
            float e = __expf(sc[t][s] - m);
            sc[t][s] = e;
            ssum += e;
        }
        #pragma unroll
        for (int o = 16; o > 0; o >>= 1) ssum += __shfl_xor_sync(0xffffffffu, ssum, o);
        __syncthreads();
        if ((tid & 31) == 0) red[tid >> 5] = ssum;
        __syncthreads();
        if (tid == 0)
            inv[t] = 1.0f / (red[0] + red[1] + red[2] + red[3] + red[4] + red[5] + red[6] + red[7]);
        __syncthreads();
    }

    // V phase: 4 s-groups x 64 d; each V element reused for all 4 tokens
    {
        int sg = tid >> 6, d = tid & 63;
        int chunk = (slen + 3) >> 2;
        int s0 = sg * chunk;
        int s1 = min(slen, s0 + chunk);
        const float* vp = vc + (size_t)b * L * E + h * D + d;
        float a0 = 0.f, a1 = 0.f, a2 = 0.f, a3 = 0.f;
        int s = s0;
        for (; s + 2 <= s1; s += 2) {
            float v0 = vp[(size_t)s * E];
            float v1 = vp[(size_t)(s + 1) * E];
            a0 += sc[0][s] * v0 + sc[0][s+1] * v1;
            a1 += sc[1][s] * v0 + sc[1][s+1] * v1;
            a2 += sc[2][s] * v0 + sc[2][s+1] * v1;
            a3 += sc[3][s] * v0 + sc[3][s+1] * v1;
        }
        if (s < s1) {
            float v0 = vp[(size_t)s * E];
            a0 += sc[0][s] * v0;
            a1 += sc[1][s] * v0;
            a2 += sc[2][s] * v0;
            a3 += sc[3][s] * v0;
        }
        vpart[sg][0][d] = a0;
        vpart[sg][1][d] = a1;
        vpart[sg][2][d] = a2;
        vpart[sg][3][d] = a3;
    }
    __syncthreads();
    {
        int t = tid >> 6, d = tid & 63;
        float sum = vpart[0][t][d] + vpart[1][t][d] + vpart[2][t][d] + vpart[3][t][d];
        out[((size_t)(b * T + t) * E) + h * D + d] = sum * inv[t];
    }
}

__global__ void eos_kernel(const float* __restrict__ x,
                           const float* __restrict__ ew,
                           const float* __restrict__ eb,
                           float* __restrict__ out_eos)
{
    int tok = blockIdx.x;
    int tid = threadIdx.x;
    float s = 0.f;
    #pragma unroll
    for (int j = 0; j < 4; j++) {
        int idx = tid + 256 * j;
        s += x[(size_t)tok * E + idx] * ew[idx];
    }
    #pragma unroll
    for (int o = 16; o > 0; o >>= 1) s += __shfl_xor_sync(0xffffffffu, s, o);
    __shared__ float red[8];
    if ((tid & 31) == 0) red[tid >> 5] = s;
    __syncthreads();
    if (tid == 0)
        out_eos[tok] = red[0]+red[1]+red[2]+red[3]+red[4]+red[5]+red[6]+red[7] + eb[0];
}

__global__ void pos_kernel(const int* __restrict__ positions, float* __restrict__ out)
{
    int i = threadIdx.x;
    if (i < NL * B) out[i] = (float)(positions[i] + T);
}

extern "C" void kernel_launch(void* const* d_in, const int* in_sizes, int n_in,
                              void* d_out, int out_size)
{
    const float* seq       = (const float*)d_in[0];
    const float* bos       = (const float*)d_in[1];
    const float* caches    = (const float*)d_in[2];
    const int*   positions = (const int*)  d_in[3];
    const float* in_w      = (const float*)d_in[4];
    const float* ip_w      = (const float*)d_in[5];
    const float* op_w      = (const float*)d_in[6];
    const float* n1w       = (const float*)d_in[7];
    const float* n1b       = (const float*)d_in[8];
    const float* n2w       = (const float*)d_in[9];
    const float* n2b       = (const float*)d_in[10];
    const float* l1_w      = (const float*)d_in[11];
    const float* l2_w      = (const float*)d_in[12];
    const float* on_w      = (const float*)d_in[13];
    const float* on_b      = (const float*)d_in[14];
    const float* eos_w     = (const float*)d_in[15];
    const float* eos_b     = (const float*)d_in[16];

    float* out = (float*)d_out;
    const size_t cache_elems = (size_t)NL * 2 * B * L * E;
    float* out_x     = out;
    float* out_eos   = out + (size_t)NTOK * E;
    float* out_cache = out_eos + NTOK;
    float* out_pos   = out_cache + cache_elems;

    float *px, *pxn, *pqkv, *pattn, *ph, *pseq, *ppart;
    cudaGetSymbolAddress((void**)&px,    g_x);
    cudaGetSymbolAddress((void**)&pxn,   g_xn);
    cudaGetSymbolAddress((void**)&pqkv,  g_qkv);
    cudaGetSymbolAddress((void**)&pattn, g_attn);
    cudaGetSymbolAddress((void**)&ph,    g_h);
    cudaGetSymbolAddress((void**)&pseq,  g_seq);
    cudaGetSymbolAddress((void**)&ppart, g_part);

    long nf4 = (long)(cache_elems / 4);
    cache_copy_kernel<<<(unsigned)((nf4 + 255) / 256), 256>>>((const float4*)caches,
                                                              (float4*)out_cache, nf4);

    prep_seq_kernel<<<4, 256>>>(seq, bos, pseq);
    gemv_kernel<0,0,1><<<dim3(E / 32, 1), 256>>>(pseq, in_w, px, nullptr, INDIM, E);

    for (int i = 0; i < NL; i++) {
        const float* ipw = ip_w + (size_t)i * 3 * E * E;
        const float* opw = op_w + (size_t)i * E * E;
        const float* l1  = l1_w + (size_t)i * FF * E;
        const float* l2  = l2_w + (size_t)i * E * FF;
        float* kcache = out_cache + ((size_t)i * 2 + 0) * B * L * E;
        float* vcache = out_cache + ((size_t)i * 2 + 1) * B * L * E;
        const int* posl = positions + i * B;

        ln_kernel<<<NTOK, 256>>>(px, n1w + (size_t)i * E, n1b + (size_t)i * E, pxn);

        // qkv: K=1024, N=3072, split-K=2 -> 192 blocks
        gemv_kernel<0,0,2><<<dim3(3 * E / 32, 2), 256>>>(pxn, ipw, nullptr, ppart, E, 3 * E);
        reduce_kernel<0,0,2><<<(32 * 3 * E + 255) / 256, 256>>>(ppart, pqkv, 3 * E);

        rope_scatter_kernel<<<64, 256>>>(pqkv, posl, kcache, vcache);
        attn_kernel<<<B * H, 256>>>(pqkv, kcache, vcache, posl, pattn);

        // op: K=1024, N=1024, split-K=4 -> 128 blocks, accumulate into x
        gemv_kernel<0,0,4><<<dim3(E / 32, 4), 256>>>(pattn, opw, nullptr, ppart, E, E);
        reduce_kernel<0,1,4><<<(32 * E + 255) / 256, 256>>>(ppart, px, E);

        ln_kernel<<<NTOK, 256>>>(px, n2w + (size_t)i * E, n2b + (size_t)i * E, pxn);

        // l1: K=1024, N=4096 -> 128 blocks, gelu
        gemv_kernel<1,0,1><<<dim3(FF / 32, 1), 256>>>(pxn, l1, ph, nullptr, E, FF);

        // l2: K=4096, N=1024, split-K=4 -> 128 blocks, accumulate into x
        gemv_kernel<0,0,4><<<dim3(E / 32, 4), 256>>>(ph, l2, nullptr, ppart, FF, E);
        reduce_kernel<0,1,4><<<(32 * E + 255) / 256, 256>>>(ppart, px, E);
    }

    ln_kernel<<<NTOK, 256>>>(px, on_w, on_b, out_x);
    eos_kernel<<<NTOK, 256>>>(out_x, eos_w, eos_b, out_eos);
    pos_kernel<<<1, 64>>>(positions, out_pos);
}

// round 3
// speedup vs baseline: 4.9455x; 1.2475x over previous
#include <cuda_runtime.h>
#include <cuda_bf16.h>
#include <math.h>

#define NL 6
#define B  8
#define T  4
#define L  2048
#define H  16
#define D  64
#define E  1024
#define FF 4096
#define INDIM 32
#define NTOK 32

// -------- scratch (device globals) --------
__device__ float g_x   [NTOK * E];
__device__ float g_xn  [NTOK * E];
__device__ float g_q   [NTOK * E];
__device__ float g_attn[NTOK * E];
__device__ float g_h   [NTOK * FF];
__device__ float g_seq [NTOK * INDIM];
__device__ float g_part[8 * NTOK * FF / 2];        // split-K partials (max 8*32*2048? use 4*32*3072=393216; size 524288)
__device__ float g_po  [B * H * 4 * T * D];        // attn partial outputs
__device__ float g_m   [B * H * 4 * T];
__device__ float g_l   [B * H * 4 * T];

// -------- f32x2 helpers --------
__device__ __forceinline__ unsigned long long pk2(float lo, float hi) {
    unsigned long long r;
    asm("mov.b64 %0, {%1, %2};" : "=l"(r) : "f"(lo), "f"(hi));
    return r;
}
__device__ __forceinline__ void fma2(unsigned long long& d,
                                     unsigned long long a,
                                     unsigned long long b) {
    asm("fma.rn.f32x2 %0, %1, %2, %3;" : "=l"(d) : "l"(a), "l"(b), "l"(d));
}
__device__ __forceinline__ float2 upk(unsigned long long v) {
    float2 f;
    asm("mov.b64 {%0, %1}, %2;" : "=f"(f.x), "=f"(f.y) : "l"(v));
    return f;
}

// -------- bulk cache copy with NaN cleaning --------
__global__ void cache_copy_kernel(const float4* __restrict__ in,
                                  float4* __restrict__ out, long n)
{
    long i = (long)blockIdx.x * blockDim.x + threadIdx.x;
    if (i < n) {
        float4 v = in[i];
        v.x = isnan(v.x) ? 0.0f : v.x;
        v.y = isnan(v.y) ? 0.0f : v.y;
        v.z = isnan(v.z) ? 0.0f : v.z;
        v.w = isnan(v.w) ? 0.0f : v.w;
        out[i] = v;
    }
}

__global__ void prep_seq_kernel(const float* __restrict__ seq,
                                const float* __restrict__ bos,
                                float* __restrict__ out)
{
    int i = blockIdx.x * 256 + threadIdx.x;
    float v = seq[i];
    out[i] = isnan(v) ? bos[i & (INDIM - 1)] : v;
}

// ======== GEMM: Y[32,N] = X[32,K] @ W[N,K]^T ========
// 64 cols per block, 256 threads (8 warps x 8 cols), lane = row.
// f32x2 packed over k-pairs. Grid (N/64, KSPLIT).
template<int ACT, int ACC, int KSPLIT>
__global__ void gemv64_kernel(const float* __restrict__ X,
                              const float* __restrict__ W,
                              float* __restrict__ Y,
                              float* __restrict__ part,
                              int K, int N)
{
    __shared__ alignas(16) float Ws[64][36];
    __shared__ alignas(16) unsigned long long XsP[16][33];

    const int t    = threadIdx.x;
    const int lane = t & 31;
    const int c0   = (t >> 5) * 8;
    const int n0   = blockIdx.x * 64;
    const int Kc   = K / KSPLIT;
    const int kbase = blockIdx.y * Kc;
    const int nch  = Kc >> 5;

    const int xrow = t >> 3, xk = (t & 7) * 4;
    const int wrow = t >> 2, wk = (t & 3) * 8;

    const float4* xg = (const float4*)(X + (size_t)xrow * K + kbase + xk);
    const float4* wg = (const float4*)(W + (size_t)(n0 + wrow) * K + kbase + wk);
    float4 xr  = *xg;
    float4 wr0 = wg[0];
    float4 wr1 = wg[1];

    unsigned long long acc[8];
    #pragma unroll
    for (int c = 0; c < 8; c++) acc[c] = 0ULL;

    for (int ch = 0; ch < nch; ch++) {
        XsP[(xk >> 1)    ][xrow] = pk2(xr.x, xr.y);
        XsP[(xk >> 1) + 1][xrow] = pk2(xr.z, xr.w);
        *(float4*)&Ws[wrow][wk]     = wr0;
        *(float4*)&Ws[wrow][wk + 4] = wr1;
        __syncthreads();
        if (ch + 1 < nch) { xg += 8; wg += 8; xr = *xg; wr0 = wg[0]; wr1 = wg[1]; }

        #pragma unroll
        for (int k2 = 0; k2 < 16; k2 += 2) {
            unsigned long long x0 = XsP[k2][lane];
            unsigned long long x1 = XsP[k2 + 1][lane];
            #pragma unroll
            for (int c = 0; c < 8; c++) {
                longlong2 w = *(const longlong2*)&Ws[c0 + c][k2 * 2];
                fma2(acc[c], x0, (unsigned long long)w.x);
                fma2(acc[c], x1, (unsigned long long)w.y);
            }
        }
        __syncthreads();
    }

    if (KSPLIT == 1) {
        #pragma unroll
        for (int c = 0; c < 8; c++) {
            float2 p = upk(acc[c]);
            float v = p.x + p.y;
            if (ACT == 1) v = 0.5f * v * (1.0f + erff(v * 0.70710678118654752f));
            float* pp = Y + (size_t)lane * N + n0 + c0 + c;
            if (ACC) *pp += v; else *pp = v;
        }
    } else {
        float* pp = part + ((size_t)blockIdx.y * 32 + lane) * N + n0 + c0;
        #pragma unroll
        for (int c = 0; c < 8; c++) {
            float2 p = upk(acc[c]);
            pp[c] = p.x + p.y;
        }
    }
}

// sum split-K partials, optional gelu / accumulate
template<int ACT, int ACC, int KS>
__global__ void reduce_kernel(const float* __restrict__ part,
                              float* __restrict__ Y, int N)
{
    int i = blockIdx.x * 256 + threadIdx.x;
    if (i >= 32 * N) return;
    int r = i / N, n = i - r * N;
    float s = 0.f;
    #pragma unroll
    for (int k = 0; k < KS; k++) s += part[((size_t)k * 32 + r) * N + n];
    if (ACT == 1) s = 0.5f * s * (1.0f + erff(s * 0.70710678118654752f));
    if (ACC) Y[i] += s; else Y[i] = s;
}

// -------- fused qkv split-K reduce + RoPE + cache scatter --------
// partials: 4 splits of [32, 3072]. q -> g_q, k/v -> caches.
__global__ void reduce_rope_kernel(const float* __restrict__ part,
                                   const int* __restrict__ pos_l,
                                   float* __restrict__ qout,
                                   float* __restrict__ kcache,
                                   float* __restrict__ vcache)
{
    int id = blockIdx.x * 256 + threadIdx.x;  // 49152 pairs
    int tok = id / 1536;
    int f2  = id - tok * 1536;
    int f   = f2 * 2;
    float s0 = 0.f, s1 = 0.f;
    #pragma unroll
    for (int k = 0; k < 4; k++) {
        const float* p = part + ((size_t)(k * 32 + tok) * 3072) + f;
        s0 += p[0];
        s1 += p[1];
    }
    int b = tok >> 2, t = tok & 3;
    int pos = pos_l[b];
    if (f < E) {                       // q: rope, store
        int dd = f & 63;
        int j = dd >> 1;
        float freq = __expf(-(float)j * (logf(10000.0f) / 32.0f));
        float sn, cs;
        sincosf((float)(pos + t) * freq, &sn, &cs);
        qout[(size_t)tok * E + f]     = s0 * cs - s1 * sn;
        qout[(size_t)tok * E + f + 1] = s0 * sn + s1 * cs;
    } else if (f < 2 * E) {            // k: rope, scatter
        int fk = f - E;
        int dd = fk & 63;
        int j = dd >> 1;
        float freq = __expf(-(float)j * (logf(10000.0f) / 32.0f));
        float sn, cs;
        sincosf((float)(pos + t) * freq, &sn, &cs);
        int slot = (pos + t) % L;
        size_t off = ((size_t)b * L + slot) * E + fk;
        kcache[off]     = s0 * cs - s1 * sn;
        kcache[off + 1] = s0 * sn + s1 * cs;
    } else {                           // v: scatter
        int fv = f - 2 * E;
        int slot = (pos + t) % L;
        size_t off = ((size_t)b * L + slot) * E + fv;
        vcache[off]     = s0;
        vcache[off + 1] = s1;
    }
}

// -------- LayerNorm, one block(256) per token --------
__global__ void ln_kernel(const float* __restrict__ X,
                          const float* __restrict__ w,
                          const float* __restrict__ b,
                          float* __restrict__ Y)
{
    int tok = blockIdx.x;
    int tid = threadIdx.x;
    const float* x = X + (size_t)tok * E;
    float v[4];
    float s = 0.f;
    #pragma unroll
    for (int j = 0; j < 4; j++) { v[j] = x[tid + 256 * j]; s += v[j]; }
    #pragma unroll
    for (int o = 16; o > 0; o >>= 1) s += __shfl_xor_sync(0xffffffffu, s, o);
    __shared__ float ws[8];
    if ((tid & 31) == 0) ws[tid >> 5] = s;
    __syncthreads();
    float mean = (ws[0]+ws[1]+ws[2]+ws[3]+ws[4]+ws[5]+ws[6]+ws[7]) * (1.0f / E);
    float s2 = 0.f;
    #pragma unroll
    for (int j = 0; j < 4; j++) { float d = v[j] - mean; s2 += d * d; }
    #pragma unroll
    for (int o = 16; o > 0; o >>= 1) s2 += __shfl_xor_sync(0xffffffffu, s2, o);
    __syncthreads();
    if ((tid & 31) == 0) ws[tid >> 5] = s2;
    __syncthreads();
    float var = (ws[0]+ws[1]+ws[2]+ws[3]+ws[4]+ws[5]+ws[6]+ws[7]) * (1.0f / E);
    float r = rsqrtf(var + 1e-5f);
    #pragma unroll
    for (int j = 0; j < 4; j++) {
        int idx = tid + 256 * j;
        Y[(size_t)tok * E + idx] = (v[j] - mean) * r * w[idx] + b[idx];
    }
}

// -------- final LayerNorm fused with eos dot --------
__global__ void ln_eos_kernel(const float* __restrict__ X,
                              const float* __restrict__ w,
                              const float* __restrict__ b,
                              const float* __restrict__ ew,
                              const float* __restrict__ eb,
                              float* __restrict__ Y,
                              float* __restrict__ out_eos)
{
    int tok = blockIdx.x;
    int tid = threadIdx.x;
    const float* x = X + (size_t)tok * E;
    float v[4];
    float s = 0.f;
    #pragma unroll
    for (int j = 0; j < 4; j++) { v[j] = x[tid + 256 * j]; s += v[j]; }
    #pragma unroll
    for (int o = 16; o > 0; o >>= 1) s += __shfl_xor_sync(0xffffffffu, s, o);
    __shared__ float ws[8];
    if ((tid & 31) == 0) ws[tid >> 5] = s;
    __syncthreads();
    float mean = (ws[0]+ws[1]+ws[2]+ws[3]+ws[4]+ws[5]+ws[6]+ws[7]) * (1.0f / E);
    float s2 = 0.f;
    #pragma unroll
    for (int j = 0; j < 4; j++) { float d = v[j] - mean; s2 += d * d; }
    #pragma unroll
    for (int o = 16; o > 0; o >>= 1) s2 += __shfl_xor_sync(0xffffffffu, s2, o);
    __syncthreads();
    if ((tid & 31) == 0) ws[tid >> 5] = s2;
    __syncthreads();
    float var = (ws[0]+ws[1]+ws[2]+ws[3]+ws[4]+ws[5]+ws[6]+ws[7]) * (1.0f / E);
    float r = rsqrtf(var + 1e-5f);
    float ed = 0.f;
    #pragma unroll
    for (int j = 0; j < 4; j++) {
        int idx = tid + 256 * j;
        float y = (v[j] - mean) * r * w[idx] + b[idx];
        Y[(size_t)tok * E + idx] = y;
        ed += y * ew[idx];
    }
    #pragma unroll
    for (int o = 16; o > 0; o >>= 1) ed += __shfl_xor_sync(0xffffffffu, ed, o);
    __syncthreads();
    if ((tid & 31) == 0) ws[tid >> 5] = ed;
    __syncthreads();
    if (tid == 0)
        out_eos[tok] = ws[0]+ws[1]+ws[2]+ws[3]+ws[4]+ws[5]+ws[6]+ws[7] + eb[0];
}

// -------- Attention partial: grid (B*H, 4 s-chunks), 256 threads --------
#define CMAX 260
__global__ void attn_part_kernel(const float* __restrict__ q,
                                 const float* __restrict__ kc,
                                 const float* __restrict__ vc,
                                 const int* __restrict__ pos_l,
                                 float* __restrict__ po,
                                 float* __restrict__ gm,
                                 float* __restrict__ gl)
{
    __shared__ float qs[4][64];
    __shared__ float sc[4][CMAX];
    __shared__ float red[8];
    __shared__ float mt[4], lt[4];
    __shared__ float vpart[4][4][64];

    int bh = blockIdx.x;
    int cidx = blockIdx.y;
    int b = bh >> 4, h = bh & 15;
    int tid = threadIdx.x;
    int pos = pos_l[b];
    int slen = pos + T;
    int chunk = (slen + 3) >> 2;
    int s0 = cidx * chunk;
    int s1 = min(slen, s0 + chunk);
    int len = s1 - s0;
    int gbase = (bh * 4 + cidx) * 4;

    if (len <= 0) {
        po[(size_t)gbase * 64 + tid] = 0.f;       // 256 floats = 4t x 64d
        if (tid < 4) { gm[gbase + tid] = -1e30f; gl[gbase + tid] = 0.f; }
        return;
    }

    {
        int t = tid >> 6, d = tid & 63;
        qs[t][d] = q[((size_t)(b * T + t) * E) + h * D + d];
    }
    __syncthreads();

    const float scale = 0.125f;
    for (int i = tid; i < len; i += 256) {
        int s = s0 + i;
        const float4* kr = (const float4*)(kc + ((size_t)b * L + s) * E + h * D);
        float d0 = 0.f, d1 = 0.f, d2 = 0.f, d3 = 0.f;
        #pragma unroll
        for (int i4 = 0; i4 < 16; i4++) {
            float4 kv = kr[i4];
            int d = i4 * 4;
            d0 += qs[0][d] * kv.x + qs[0][d+1] * kv.y + qs[0][d+2] * kv.z + qs[0][d+3] * kv.w;
            d1 += qs[1][d] * kv.x + qs[1][d+1] * kv.y + qs[1][d+2] * kv.z + qs[1][d+3] * kv.w;
            d2 += qs[2][d] * kv.x + qs[2][d+1] * kv.y + qs[2][d+2] * kv.z + qs[2][d+3] * kv.w;
            d3 += qs[3][d] * kv.x + qs[3][d+1] * kv.y + qs[3][d+2] * kv.z + qs[3][d+3] * kv.w;
        }
        sc[0][i] = (s <= pos + 0) ? d0 * scale : -1e30f;
        sc[1][i] = (s <= pos + 1) ? d1 * scale : -1e30f;
        sc[2][i] = (s <= pos + 2) ? d2 * scale : -1e30f;
        sc[3][i] = (s <= pos + 3) ? d3 * scale : -1e30f;
    }
    __syncthreads();

    #pragma unroll
    for (int t = 0; t < 4; t++) {
        float m = -1e30f;
        for (int i = tid; i < len; i += 256) m = fmaxf(m, sc[t][i]);
        #pragma unroll
        for (int o = 16; o > 0; o >>= 1) m = fmaxf(m, __shfl_xor_sync(0xffffffffu, m, o));
        if ((tid & 31) == 0) red[tid >> 5] = m;
        __syncthreads();
        m = fmaxf(fmaxf(fmaxf(red[0], red[1]), fmaxf(red[2], red[3])),
                  fmaxf(fmaxf(red[4], red[5]), fmaxf(red[6], red[7])));
        float ssum = 0.f;
        for (int i = tid; i < len; i += 256) {
            float e = __expf(sc[t][i] - m);
            sc[t][i] = e;
            ssum += e;
        }
        #pragma unroll
        for (int o = 16; o > 0; o >>= 1) ssum += __shfl_xor_sync(0xffffffffu, ssum, o);
        __syncthreads();
        if ((tid & 31) == 0) red[tid >> 5] = ssum;
        __syncthreads();
        if (tid == 0) {
            mt[t] = m;
            lt[t] = red[0]+red[1]+red[2]+red[3]+red[4]+red[5]+red[6]+red[7];
        }
        __syncthreads();
    }

    // partial V accumulation: 4 s-subgroups x 64 d
    {
        int sg = tid >> 6, d = tid & 63;
        int q4 = (len + 3) >> 2;
        int i0 = sg * q4;
        int i1 = min(len, i0 + q4);
        const float* vp = vc + ((size_t)b * L + s0) * E + h * D + d;
        float a0 = 0.f, a1 = 0.f, a2 = 0.f, a3 = 0.f;
        int i = i0;
        for (; i + 2 <= i1; i += 2) {
            float v0 = vp[(size_t)i * E];
            float v1 = vp[(size_t)(i + 1) * E];
            a0 += sc[0][i] * v0 + sc[0][i+1] * v1;
            a1 += sc[1][i] * v0 + sc[1][i+1] * v1;
            a2 += sc[2][i] * v0 + sc[2][i+1] * v1;
            a3 += sc[3][i] * v0 + sc[3][i+1] * v1;
        }
        if (i < i1) {
            float v0 = vp[(size_t)i * E];
            a0 += sc[0][i] * v0;
            a1 += sc[1][i] * v0;
            a2 += sc[2][i] * v0;
            a3 += sc[3][i] * v0;
        }
        vpart[sg][0][d] = a0;
        vpart[sg][1][d] = a1;
        vpart[sg][2][d] = a2;
        vpart[sg][3][d] = a3;
    }
    __syncthreads();
    {
        int t = tid >> 6, d = tid & 63;
        float sum = vpart[0][t][d] + vpart[1][t][d] + vpart[2][t][d] + vpart[3][t][d];
        po[((size_t)(gbase + t)) * 64 + d] = sum;
        if (tid < 4) { gm[gbase + tid] = mt[tid]; gl[gbase + tid] = lt[tid]; }
    }
}

// -------- Attention combine: grid B*H, 256 threads --------
__global__ void attn_comb_kernel(const float* __restrict__ po,
                                 const float* __restrict__ gm,
                                 const float* __restrict__ gl,
                                 float* __restrict__ out)
{
    int bh = blockIdx.x;
    int b = bh >> 4, h = bh & 15;
    int tid = threadIdx.x;
    int t = tid >> 6, d = tid & 63;

    float m0 = gm[(bh * 4 + 0) * 4 + t];
    float m1 = gm[(bh * 4 + 1) * 4 + t];
    float m2 = gm[(bh * 4 + 2) * 4 + t];
    float m3 = gm[(bh * 4 + 3) * 4 + t];
    float M = fmaxf(fmaxf(m0, m1), fmaxf(m2, m3));
    float w0 = __expf(m0 - M), w1 = __expf(m1 - M);
    float w2 = __expf(m2 - M), w3 = __expf(m3 - M);
    float l = w0 * gl[(bh * 4 + 0) * 4 + t] + w1 * gl[(bh * 4 + 1) * 4 + t]
            + w2 * gl[(bh * 4 + 2) * 4 + t] + w3 * gl[(bh * 4 + 3) * 4 + t];
    float o = w0 * po[((size_t)(bh * 4 + 0) * 4 + t) * 64 + d]
            + w1 * po[((size_t)(bh * 4 + 1) * 4 + t) * 64 + d]
            + w2 * po[((size_t)(bh * 4 + 2) * 4 + t) * 64 + d]
            + w3 * po[((size_t)(bh * 4 + 3) * 4 + t) * 64 + d];
    out[((size_t)(b * T + t) * E) + h * D + d] = o / l;
}

__global__ void pos_kernel(const int* __restrict__ positions, float* __restrict__ out)
{
    int i = threadIdx.x;
    if (i < NL * B) out[i] = (float)(positions[i] + T);
}

extern "C" void kernel_launch(void* const* d_in, const int* in_sizes, int n_in,
                              void* d_out, int out_size)
{
    const float* seq       = (const float*)d_in[0];
    const float* bos       = (const float*)d_in[1];
    const float* caches    = (const float*)d_in[2];
    const int*   positions = (const int*)  d_in[3];
    const float* in_w      = (const float*)d_in[4];
    const float* ip_w      = (const float*)d_in[5];
    const float* op_w      = (const float*)d_in[6];
    const float* n1w       = (const float*)d_in[7];
    const float* n1b       = (const float*)d_in[8];
    const float* n2w       = (const float*)d_in[9];
    const float* n2b       = (const float*)d_in[10];
    const float* l1_w      = (const float*)d_in[11];
    const float* l2_w      = (const float*)d_in[12];
    const float* on_w      = (const float*)d_in[13];
    const float* on_b      = (const float*)d_in[14];
    const float* eos_w     = (const float*)d_in[15];
    const float* eos_b     = (const float*)d_in[16];

    float* out = (float*)d_out;
    const size_t cache_elems = (size_t)NL * 2 * B * L * E;
    float* out_x     = out;
    float* out_eos   = out + (size_t)NTOK * E;
    float* out_cache = out_eos + NTOK;
    float* out_pos   = out_cache + cache_elems;

    float *px, *pxn, *pq, *pattn, *ph, *pseq, *ppart, *ppo, *pm, *pl;
    cudaGetSymbolAddress((void**)&px,    g_x);
    cudaGetSymbolAddress((void**)&pxn,   g_xn);
    cudaGetSymbolAddress((void**)&pq,    g_q);
    cudaGetSymbolAddress((void**)&pattn, g_attn);
    cudaGetSymbolAddress((void**)&ph,    g_h);
    cudaGetSymbolAddress((void**)&pseq,  g_seq);
    cudaGetSymbolAddress((void**)&ppart, g_part);
    cudaGetSymbolAddress((void**)&ppo,   g_po);
    cudaGetSymbolAddress((void**)&pm,    g_m);
    cudaGetSymbolAddress((void**)&pl,    g_l);

    long nf4 = (long)(cache_elems / 4);
    cache_copy_kernel<<<(unsigned)((nf4 + 255) / 256), 256>>>((const float4*)caches,
                                                              (float4*)out_cache, nf4);

    prep_seq_kernel<<<4, 256>>>(seq, bos, pseq);
    gemv64_kernel<0,0,1><<<dim3(E / 64, 1), 256>>>(pseq, in_w, px, nullptr, INDIM, E);

    for (int i = 0; i < NL; i++) {
        const float* ipw = ip_w + (size_t)i * 3 * E * E;
        const float* opw = op_w + (size_t)i * E * E;
        const float* l1  = l1_w + (size_t)i * FF * E;
        const float* l2  = l2_w + (size_t)i * E * FF;
        float* kcache = out_cache + ((size_t)i * 2 + 0) * B * L * E;
        float* vcache = out_cache + ((size_t)i * 2 + 1) * B * L * E;
        const int* posl = positions + i * B;

        ln_kernel<<<NTOK, 256>>>(px, n1w + (size_t)i * E, n1b + (size_t)i * E, pxn);

        // qkv: K=1024, N=3072, split-K=4 -> 48x4 = 192 blocks
        gemv64_kernel<0,0,4><<<dim3(3 * E / 64, 4), 256>>>(pxn, ipw, nullptr, ppart, E, 3 * E);
        reduce_rope_kernel<<<192, 256>>>(ppart, posl, pq, kcache, vcache);

        attn_part_kernel<<<dim3(B * H, 4), 256>>>(pq, kcache, vcache, posl, ppo, pm, pl);
        attn_comb_kernel<<<B * H, 256>>>(ppo, pm, pl, pattn);

        // op: K=1024, N=1024, split-K=8 -> 16x8 = 128 blocks
        gemv64_kernel<0,0,8><<<dim3(E / 64, 8), 256>>>(pattn, opw, nullptr, ppart, E, E);
        reduce_kernel<0,1,8><<<(32 * E + 255) / 256, 256>>>(ppart, px, E);

        ln_kernel<<<NTOK, 256>>>(px, n2w + (size_t)i * E, n2b + (size_t)i * E, pxn);

        // l1: K=1024, N=4096, split-K=2 -> 64x2 = 128 blocks, gelu in reduce
        gemv64_kernel<0,0,2><<<dim3(FF / 64, 2), 256>>>(pxn, l1, nullptr, ppart, E, FF);
        reduce_kernel<1,0,2><<<(32 * FF + 255) / 256, 256>>>(ppart, ph, FF);

        // l2: K=4096, N=1024, split-K=8 -> 16x8 = 128 blocks
        gemv64_kernel<0,0,8><<<dim3(E / 64, 8), 256>>>(ph, l2, nullptr, ppart, FF, E);
        reduce_kernel<0,1,8><<<(32 * E + 255) / 256, 256>>>(ppart, px, E);
    }

    ln_eos_kernel<<<NTOK, 256>>>(px, on_w, on_b, eos_w, eos_b, out_x, out_eos);
    pos_kernel<<<1, 64>>>(positions, out_pos);
}